// round 1
// baseline (speedup 1.0000x reference)
#include <cuda_runtime.h>
#include <mma.h>
#include <cstdint>

using namespace nvcuda;

// Problem constants
#define BATCH   32768
#define TSTEPS  30
#define HID     384
#define KA      512     // concat K: [x(128) | hidden(384)]
#define NG      1536    // 4 gate column-groups of 384: r, z, inn, hn
#define MR      32      // batch rows per CTA
#define NTH     256     // threads per CTA (8 warps)
#define LDA     516     // sA row stride (pad from 512)
#define LDGT    132     // sG row stride (pad from 128)

// -------- device scratch (static; no allocation allowed) --------
__device__ float g_WcatT[KA * NG];   // [k][j], row-major, pre-rounded to tf32
__device__ float g_bcat[NG];
__device__ float g_Wd1T[HID * 64];   // Wd1 transposed: [k][j]

// -------- prep kernel: build combined GEMM weights --------
__global__ void prep_kernel(const float* __restrict__ W_ih, const float* __restrict__ b_ih,
                            const float* __restrict__ W_hh, const float* __restrict__ b_hh,
                            const float* __restrict__ Wd1) {
    int tid = blockIdx.x * blockDim.x + threadIdx.x;
    int stride = gridDim.x * blockDim.x;

    // WcatT[k][j]:
    //  j in [0,768)    : r,z gates  -> k<128: W_ih[j][k], else W_hh[j][k-128]
    //  j in [768,1152) : inn        -> k<128: W_ih[j][k], else 0
    //  j in [1152,1536): hn         -> k<128: 0,          else W_hh[j-384][k-128]
    for (int e = tid; e < KA * NG; e += stride) {
        int k = e / NG;
        int j = e - k * NG;
        float v;
        if (j < 768) {
            v = (k < 128) ? W_ih[j * 128 + k] : W_hh[j * HID + (k - 128)];
        } else if (j < 1152) {
            v = (k < 128) ? W_ih[j * 128 + k] : 0.0f;
        } else {
            v = (k < 128) ? 0.0f : W_hh[(j - 384) * HID + (k - 128)];
        }
        g_WcatT[e] = wmma::__float_to_tf32(v);
    }
    for (int j = tid; j < NG; j += stride) {
        float bv;
        if (j < 768)        bv = b_ih[j] + b_hh[j];
        else if (j < 1152)  bv = b_ih[j];
        else                bv = b_hh[j - 384];
        g_bcat[j] = bv;
    }
    for (int e = tid; e < HID * 64; e += stride) {
        int k = e >> 6;
        int j = e & 63;
        g_Wd1T[e] = Wd1[j * HID + k];   // transpose for coalesced decode loads
    }
}

__device__ __forceinline__ float sigmoidf_fast(float x) {
    return 1.0f / (1.0f + __expf(-x));
}
__device__ __forceinline__ float tanhf_fast(float x) {
    // 2/(1+e^{-2x}) - 1 : saturates correctly for |x| large (no NaN)
    return 2.0f / (1.0f + __expf(-2.0f * x)) - 1.0f;
}

// -------- main fused GRU rollout kernel --------
__global__ __launch_bounds__(NTH, 1)
void gru_kernel(const float* __restrict__ init_hidden,
                const float* __restrict__ plan,
                const float* __restrict__ gate,
                const float* __restrict__ init_state,
                const float* __restrict__ Wp, const float* __restrict__ bp,
                const float* __restrict__ Ws, const float* __restrict__ bs,
                const float* __restrict__ bd1,
                const float* __restrict__ Wd2, const float* __restrict__ bd2,
                float* __restrict__ out) {
    extern __shared__ float sm[];
    float* sA    = sm;                  // [MR][LDA]  A = [x | hidden_tf32]
    float* sH    = sA    + MR * LDA;    // [MR][HID]  true fp32 hidden
    float* sG    = sH    + MR * HID;    // [MR][LDGT] gate chunk / decode tmp
    float* sBias = sG    + MR * LDGT;   // [NG]
    float* sWs   = sBias + NG;          // [128*3]
    float* sWp   = sWs   + 384;         // [128*3]
    float* sbs   = sWp   + 384;         // [128]
    float* sbp   = sbs   + 128;         // [128]
    float* sWd2  = sbp   + 128;         // [3*64]
    float* sbd1  = sWd2  + 192;         // [64]
    float* sbd2  = sbd1  + 64;          // [4]
    float* sStat = sbd2  + 4;           // [MR*3]
    float* sGate = sStat + 96;          // [MR]
    float* sPlan = sGate + 32;          // [MR*3]

    const int tid  = threadIdx.x;
    const int warp = tid >> 5;
    const int row0 = blockIdx.x * MR;

    // ---- load constants / init state ----
    for (int i = tid; i < NG; i += NTH) sBias[i] = g_bcat[i];
    for (int i = tid; i < 384; i += NTH) { sWs[i] = Ws[i]; sWp[i] = Wp[i]; }
    for (int i = tid; i < 128; i += NTH) { sbs[i] = bs[i]; sbp[i] = bp[i]; }
    if (tid < 192) sWd2[tid] = Wd2[tid];
    if (tid < 64)  sbd1[tid] = bd1[tid];
    if (tid < 3)   sbd2[tid] = bd2[tid];
    if (tid < MR * 3) sStat[tid] = init_state[(size_t)row0 * 3 + tid];
    if (tid < MR)  sGate[tid] = gate[row0 + tid];
    for (int i = tid; i < MR * HID; i += NTH) {
        float h = init_hidden[(size_t)row0 * HID + i];
        sH[i] = h;
        int r = i / HID, u = i - r * HID;
        sA[r * LDA + 128 + u] = wmma::__float_to_tf32(h);
    }
    __syncthreads();

    // warp GEMM mapping: 8 warps, each owns a 32(M) x 16(N) strip per chunk
    const int wgrp = warp >> 1;         // gate group 0..3
    const int wsub = warp & 1;          // sub-column 0..1
    const int sgcol = wgrp * 32 + wsub * 16;

    for (int t = 0; t < TSTEPS; t++) {
        // ---- load plan_t ----
        if (tid < MR * 3) {
            int r = tid / 3, d = tid - r * 3;
            sPlan[tid] = plan[((size_t)(row0 + r) * TSTEPS + t) * 3 + d];
        }
        __syncthreads();

        // ---- x = state@Ws^T + bs + (plan_t@Wp^T + bp)*gate -> sA[:, 0:128] ----
        for (int i = tid; i < MR * 128; i += NTH) {
            int r = i >> 7, c = i & 127;
            float s0 = sStat[r * 3], s1 = sStat[r * 3 + 1], s2 = sStat[r * 3 + 2];
            float p0 = sPlan[r * 3], p1 = sPlan[r * 3 + 1], p2 = sPlan[r * 3 + 2];
            float v = sbs[c] + s0 * sWs[c * 3] + s1 * sWs[c * 3 + 1] + s2 * sWs[c * 3 + 2]
                    + (sbp[c] + p0 * sWp[c * 3] + p1 * sWp[c * 3 + 1] + p2 * sWp[c * 3 + 2]) * sGate[r];
            sA[r * LDA + c] = wmma::__float_to_tf32(v);
        }
        __syncthreads();

        // ---- main GEMM, 12 N-chunks of 128 cols (u-aligned across 4 gate groups) ----
        for (int nc = 0; nc < 12; nc++) {
            const int u0 = nc * 32;
            const int jb = wgrp * 384 + u0 + wsub * 16;

            wmma::fragment<wmma::accumulator, 16, 16, 8, float> acc0, acc1;
            wmma::fill_fragment(acc0, 0.0f);
            wmma::fill_fragment(acc1, 0.0f);
            const float* Bbase = g_WcatT + jb;

            #pragma unroll 8
            for (int k = 0; k < KA; k += 8) {
                wmma::fragment<wmma::matrix_b, 16, 16, 8, wmma::precision::tf32, wmma::row_major> bf;
                wmma::load_matrix_sync(bf, Bbase + (size_t)k * NG, NG);
                wmma::fragment<wmma::matrix_a, 16, 16, 8, wmma::precision::tf32, wmma::row_major> a0, a1;
                wmma::load_matrix_sync(a0, sA + k, LDA);
                wmma::load_matrix_sync(a1, sA + 16 * LDA + k, LDA);
                wmma::mma_sync(acc0, a0, bf, acc0);
                wmma::mma_sync(acc1, a1, bf, acc1);
            }
            wmma::store_matrix_sync(sG + sgcol, acc0, LDGT, wmma::mem_row_major);
            wmma::store_matrix_sync(sG + 16 * LDGT + sgcol, acc1, LDGT, wmma::mem_row_major);
            __syncthreads();

            // ---- gate math for u in [u0, u0+32); writes new hidden into sH ----
            for (int i = tid; i < MR * 32; i += NTH) {
                int r = i >> 5, uu = i & 31;
                int u = u0 + uu;
                const float* gr = sG + r * LDGT;
                float xr  = gr[uu]       + sBias[u];
                float xz  = gr[32 + uu]  + sBias[384 + u];
                float xin = gr[64 + uu]  + sBias[768 + u];
                float xhn = gr[96 + uu]  + sBias[1152 + u];
                float rg = sigmoidf_fast(xr);
                float zg = sigmoidf_fast(xz);
                float n  = tanhf_fast(xin + rg * xhn);
                float hold = sH[r * HID + u];
                sH[r * HID + u] = (1.0f - zg) * n + zg * hold;
            }
            __syncthreads();
        }

        // ---- refresh tf32 hidden copy in sA for next step ----
        for (int i = tid; i < MR * HID; i += NTH) {
            int r = i / HID, u = i - r * HID;
            sA[r * LDA + 128 + u] = wmma::__float_to_tf32(sH[i]);
        }

        // ---- decode layer 1: tmp[32][64] = elu(h @ Wd1^T + bd1) ----
        {
            int j  = tid & 63;
            int rb = tid >> 6;           // 0..3, 8 rows each
            float acc[8];
            #pragma unroll
            for (int q = 0; q < 8; q++) acc[q] = sbd1[j];
            const float* wp = g_Wd1T + j;
            const float* hp = sH + (rb * 8) * HID;
            #pragma unroll 4
            for (int k = 0; k < HID; k++) {
                float w = wp[(size_t)k * 64];
                #pragma unroll
                for (int q = 0; q < 8; q++) acc[q] += hp[q * HID + k] * w;
            }
            #pragma unroll
            for (int q = 0; q < 8; q++) {
                float v = acc[q];
                v = v > 0.0f ? v : (__expf(v) - 1.0f);  // elu
                sG[(rb * 8 + q) * 68 + j] = v;
            }
        }
        __syncthreads();

        // ---- decode layer 2 + state update + output ----
        if (tid < MR * 3) {
            int r = tid / 3, c = tid - r * 3;
            float acc = sbd2[c];
            const float* w2 = sWd2 + c * 64;
            const float* tp = sG + r * 68;
            #pragma unroll 16
            for (int k = 0; k < 64; k++) acc += tp[k] * w2[k];
            float ns = sStat[tid] + acc;
            sStat[tid] = ns;
            out[((size_t)(row0 + r) * TSTEPS + t) * 3 + c] = ns;
        }
        __syncthreads();
    }
}

// -------- launch --------
extern "C" void kernel_launch(void* const* d_in, const int* in_sizes, int n_in,
                              void* d_out, int out_size) {
    const float* init_hidden = (const float*)d_in[0];
    const float* plan        = (const float*)d_in[1];
    const float* gatep       = (const float*)d_in[2];
    const float* init_state  = (const float*)d_in[3];
    const float* Wp   = (const float*)d_in[4];
    const float* bp   = (const float*)d_in[5];
    const float* Ws   = (const float*)d_in[6];
    const float* bs   = (const float*)d_in[7];
    const float* W_ih = (const float*)d_in[8];
    const float* b_ih = (const float*)d_in[9];
    const float* W_hh = (const float*)d_in[10];
    const float* b_hh = (const float*)d_in[11];
    const float* Wd1  = (const float*)d_in[12];
    const float* bd1  = (const float*)d_in[13];
    const float* Wd2  = (const float*)d_in[14];
    const float* bd2  = (const float*)d_in[15];
    float* out = (float*)d_out;

    prep_kernel<<<256, 256>>>(W_ih, b_ih, W_hh, b_hh, Wd1);

    const size_t smem_floats = (size_t)MR * LDA + MR * HID + MR * LDGT + NG
                             + 384 + 384 + 128 + 128 + 192 + 64 + 4 + 96 + 32 + 96;
    const size_t smem_bytes = smem_floats * sizeof(float);
    cudaFuncSetAttribute(gru_kernel, cudaFuncAttributeMaxDynamicSharedMemorySize,
                         (int)smem_bytes);

    gru_kernel<<<BATCH / MR, NTH, smem_bytes>>>(
        init_hidden, plan, gatep, init_state, Wp, bp, Ws, bs,
        bd1, Wd2, bd2, out);
}

// round 2
// speedup vs baseline: 3.8815x; 3.8815x over previous
#include <cuda_runtime.h>
#include <cstdint>

// Problem constants
#define BATCH   32768
#define TSTEPS  30
#define HID     384
#define KTOT    392     // 8 rowvec + 384 hidden
#define NKB     49      // K blocks of 8
#define NCOLS   1536    // 4 gate col-groups (r,z,n_i,n_h) x 384, u-block interleaved
#define NN8     192     // NCOLS/8
#define MROWS   64      // batch rows per CTA
#define NTH     256     // 8 warps
#define LDH     396     // sA row stride (392 + 4), mult of 4, conflict-free
#define ASZ     (MROWS*LDH)

// -------- static device scratch (no allocation allowed) --------
__device__ float2 g_B2[NKB * NN8 * 32];     // main GEMM B, fragment order
__device__ float2 g_Wd1f2[48 * 8 * 32];     // decode B, fragment order

__device__ __forceinline__ float to_tf32(float x) {
    unsigned u; asm("cvt.rna.tf32.f32 %0, %1;" : "=r"(u) : "f"(x));
    return __uint_as_float(u);
}
__device__ __forceinline__ float sigf(float x) { return 1.0f / (1.0f + __expf(-x)); }
__device__ __forceinline__ float tanhf_fast(float x) {
    return 2.0f / (1.0f + __expf(-2.0f * x)) - 1.0f;
}

__device__ __forceinline__ void mma_tf32(float* c, const unsigned* a, unsigned b0, unsigned b1) {
    asm volatile(
        "mma.sync.aligned.m16n8k8.row.col.f32.tf32.tf32.f32 "
        "{%0,%1,%2,%3}, {%4,%5,%6,%7}, {%8,%9}, {%0,%1,%2,%3};\n"
        : "+f"(c[0]), "+f"(c[1]), "+f"(c[2]), "+f"(c[3])
        : "r"(a[0]), "r"(a[1]), "r"(a[2]), "r"(a[3]), "r"(b0), "r"(b1));
}

// -------- prep: build fragment-ordered B matrices --------
// Column layout: col = ub*64 + gate*16 + uu  (ub in [0,24), gate 0=r,1=z,2=n_i,3=n_h, uu in [0,16))
// Row layout (K): k in [0,8) = rowvec coeffs [c0, c1, Ams0..2, Amp0..2]; k in [8,392) = W_hh part.
__device__ float bval(int k, int col,
                      const float* Wih, const float* bih,
                      const float* Whh, const float* bhh,
                      const float* Wp, const float* bp,
                      const float* Ws, const float* bs) {
    int u    = ((col >> 6) << 4) | (col & 15);
    int gate = (col >> 4) & 3;
    float v;
    if (k >= 8) {
        int kk = k - 8;
        if (gate == 2) v = 0.0f;                       // n_i: no hidden part
        else {
            int grow = (gate == 3 ? 768 : gate * 384) + u;
            v = Whh[grow * HID + kk];
        }
    } else {
        if (gate == 3) {
            v = (k == 0) ? bhh[768 + u] : 0.0f;        // n_h: bias-only in rowvec
        } else {
            int grow = gate * 384 + u;                 // gate 0,1,2 -> rows u,384+u,768+u
            const float* wr = Wih + grow * 128;
            float s = 0.0f;
            if (k == 0) {
                s = bih[grow] + (gate < 2 ? bhh[grow] : 0.0f);
                for (int m = 0; m < 128; m++) s += bs[m] * wr[m];
            } else if (k == 1) {
                for (int m = 0; m < 128; m++) s += bp[m] * wr[m];
            } else if (k < 5) {
                int d = k - 2;
                for (int m = 0; m < 128; m++) s += Ws[m * 3 + d] * wr[m];
            } else {
                int d = k - 5;
                for (int m = 0; m < 128; m++) s += Wp[m * 3 + d] * wr[m];
            }
            v = s;
        }
    }
    return v;
}

__global__ void prep_kernel(const float* __restrict__ W_ih, const float* __restrict__ b_ih,
                            const float* __restrict__ W_hh, const float* __restrict__ b_hh,
                            const float* __restrict__ Wp,  const float* __restrict__ bp,
                            const float* __restrict__ Ws,  const float* __restrict__ bs,
                            const float* __restrict__ Wd1) {
    int gid = blockIdx.x * blockDim.x + threadIdx.x;
    int total = (NKB * NN8 + 48 * 8) * 32;
    for (int w = gid; w < total; w += gridDim.x * blockDim.x) {
        int fid = w >> 5, lane = w & 31;
        int tig = lane & 3, g = lane >> 2;
        if (fid < NKB * NN8) {
            int kb = fid / NN8, n8 = fid - kb * NN8;
            int k0 = kb * 8 + tig;
            int col = n8 * 8 + g;
            float b0 = bval(k0,     col, W_ih, b_ih, W_hh, b_hh, Wp, bp, Ws, bs);
            float b1 = bval(k0 + 4, col, W_ih, b_ih, W_hh, b_hh, Wp, bp, Ws, bs);
            g_B2[fid * 32 + lane] = make_float2(to_tf32(b0), to_tf32(b1));
        } else {
            int f = fid - NKB * NN8;         // 48 kb * 8 n8
            int kb = f >> 3, n8 = f & 7;
            int n = n8 * 8 + g;
            int k = kb * 8 + tig;
            float b0 = Wd1[n * HID + k];
            float b1 = Wd1[n * HID + k + 4];
            g_Wd1f2[f * 32 + lane] = make_float2(to_tf32(b0), to_tf32(b1));
        }
    }
}

// -------- main fused GRU rollout --------
__global__ __launch_bounds__(NTH, 1)
void gru_kernel(const float* __restrict__ init_hidden,
                const float* __restrict__ plan,
                const float* __restrict__ gate,
                const float* __restrict__ init_state,
                const float* __restrict__ bd1,
                const float* __restrict__ Wd2,
                const float* __restrict__ bd2,
                float* __restrict__ out) {
    extern __shared__ float sm[];
    float* sA0   = sm;                  // [MROWS][LDH] ping
    float* sA1   = sA0 + ASZ;           // pong
    float* sDec  = sA1 + ASZ;           // [64][68]
    float* sStat = sDec + 64 * 68;      // [64*3]
    float* sGate = sStat + 192;         // [64]
    float* sbd1  = sGate + 64;          // [64]
    float* sWd2  = sbd1 + 64;           // [3*64]
    float* sbd2  = sWd2 + 192;          // [4]

    const int tid  = threadIdx.x;
    const int warp = tid >> 5;
    const int lane = tid & 31;
    const int g8   = lane >> 2;
    const int tig  = lane & 3;
    const int row0 = blockIdx.x * MROWS;

    // init
    for (int i = tid; i < MROWS * HID; i += NTH) {
        int r = i / HID, u = i - r * HID;
        sA0[r * LDH + 8 + u] = to_tf32(init_hidden[(size_t)row0 * HID + i]);
    }
    if (tid < 192) { sStat[tid] = init_state[(size_t)row0 * 3 + tid]; sWd2[tid] = Wd2[tid]; }
    if (tid < 64)  { sGate[tid] = gate[row0 + tid]; sbd1[tid] = bd1[tid]; }
    if (tid < 3)   sbd2[tid] = bd2[tid];
    __syncthreads();

    for (int t = 0; t < TSTEPS; t++) {
        float* Acur = (t & 1) ? sA1 : sA0;
        float* Anxt = (t & 1) ? sA0 : sA1;

        // ---- phase 0: rowvec = [1, g, S, g*P] into Acur cols 0..7 ----
        for (int i = tid; i < MROWS * 8; i += NTH) {
            int r = i >> 3, c = i & 7;
            float v;
            if (c == 0)      v = 1.0f;
            else if (c == 1) v = sGate[r];
            else if (c < 5)  v = sStat[r * 3 + (c - 2)];
            else             v = sGate[r] * plan[((size_t)(row0 + r) * TSTEPS + t) * 3 + (c - 5)];
            Acur[r * LDH + c] = to_tf32(v);
        }
        __syncthreads();

        // ---- phase 1: GEMM (64 x 1536, K=392) + gate math on fragments ----
        for (int task = 0; task < 3; task++) {
            const int ub = warp + task * 8;     // u-block 0..23
            float acc[128];
            #pragma unroll
            for (int i = 0; i < 128; i++) acc[i] = 0.0f;

            const float2* Bt = g_B2 + (size_t)(ub * 8) * 32 + lane;
            #pragma unroll 2
            for (int kb = 0; kb < NKB; kb++) {
                unsigned a[16];
                const float* Ab = Acur + kb * 8;
                #pragma unroll
                for (int mf = 0; mf < 4; mf++) {
                    int r0 = mf * 16 + g8;
                    a[mf * 4 + 0] = __float_as_uint(Ab[r0 * LDH + tig]);
                    a[mf * 4 + 1] = __float_as_uint(Ab[(r0 + 8) * LDH + tig]);
                    a[mf * 4 + 2] = __float_as_uint(Ab[r0 * LDH + tig + 4]);
                    a[mf * 4 + 3] = __float_as_uint(Ab[(r0 + 8) * LDH + tig + 4]);
                }
                const float2* Bk = Bt + (size_t)kb * NN8 * 32;
                #pragma unroll
                for (int n8i = 0; n8i < 8; n8i++) {
                    float2 bv = Bk[n8i * 32];
                    unsigned b0 = __float_as_uint(bv.x), b1 = __float_as_uint(bv.y);
                    #pragma unroll
                    for (int mf = 0; mf < 4; mf++)
                        mma_tf32(&acc[(mf * 8 + n8i) * 4], &a[mf * 4], b0, b1);
                }
            }

            // gate math directly on fragments: n8i = gate*2 + half
            #pragma unroll
            for (int mf = 0; mf < 4; mf++)
            #pragma unroll
            for (int half = 0; half < 2; half++)
            #pragma unroll
            for (int e = 0; e < 4; e++) {
                int row = mf * 16 + g8 + ((e >> 1) << 3);
                int u   = ub * 16 + half * 8 + tig * 2 + (e & 1);
                float aR  = acc[(mf * 8 + 0 + half) * 4 + e];
                float aZ  = acc[(mf * 8 + 2 + half) * 4 + e];
                float aNi = acc[(mf * 8 + 4 + half) * 4 + e];
                float aNh = acc[(mf * 8 + 6 + half) * 4 + e];
                float rg = sigf(aR);
                float zg = sigf(aZ);
                float n  = tanhf_fast(aNi + rg * aNh);
                float hold = Acur[row * LDH + 8 + u];
                float hnew = (1.0f - zg) * n + zg * hold;
                Anxt[row * LDH + 8 + u] = to_tf32(hnew);
            }
        }
        __syncthreads();

        // ---- phase 2: decode layer1 (64x64, K=384) on tensor cores ----
        {
            float dacc[16];
            #pragma unroll
            for (int i = 0; i < 16; i++) dacc[i] = 0.0f;
            #pragma unroll 2
            for (int kb = 0; kb < 48; kb++) {
                unsigned a[16];
                const float* Ab = Anxt + 8 + kb * 8;
                #pragma unroll
                for (int mf = 0; mf < 4; mf++) {
                    int r0 = mf * 16 + g8;
                    a[mf * 4 + 0] = __float_as_uint(Ab[r0 * LDH + tig]);
                    a[mf * 4 + 1] = __float_as_uint(Ab[(r0 + 8) * LDH + tig]);
                    a[mf * 4 + 2] = __float_as_uint(Ab[r0 * LDH + tig + 4]);
                    a[mf * 4 + 3] = __float_as_uint(Ab[(r0 + 8) * LDH + tig + 4]);
                }
                float2 bv = g_Wd1f2[(kb * 8 + warp) * 32 + lane];
                unsigned b0 = __float_as_uint(bv.x), b1 = __float_as_uint(bv.y);
                #pragma unroll
                for (int mf = 0; mf < 4; mf++)
                    mma_tf32(&dacc[mf * 4], &a[mf * 4], b0, b1);
            }
            #pragma unroll
            for (int mf = 0; mf < 4; mf++)
            #pragma unroll
            for (int e = 0; e < 4; e++) {
                int row = mf * 16 + g8 + ((e >> 1) << 3);
                int col = warp * 8 + tig * 2 + (e & 1);
                float v = dacc[mf * 4 + e] + sbd1[col];
                v = v > 0.0f ? v : (__expf(v) - 1.0f);   // ELU
                sDec[row * 68 + col] = v;
            }
        }
        __syncthreads();

        // ---- phase 3: decode layer2 + state update + output ----
        if (tid < 192) {
            int r = tid / 3, c = tid - r * 3;
            float acc = sbd2[c];
            const float* w2 = sWd2 + c * 64;
            const float* dp = sDec + r * 68;
            #pragma unroll 16
            for (int k = 0; k < 64; k++) acc += dp[k] * w2[k];
            float ns = sStat[tid] + acc;
            sStat[tid] = ns;
            out[((size_t)(row0 + r) * TSTEPS + t) * 3 + c] = ns;
        }
        __syncthreads();
    }
}

// -------- launch --------
extern "C" void kernel_launch(void* const* d_in, const int* in_sizes, int n_in,
                              void* d_out, int out_size) {
    const float* init_hidden = (const float*)d_in[0];
    const float* plan        = (const float*)d_in[1];
    const float* gatep       = (const float*)d_in[2];
    const float* init_state  = (const float*)d_in[3];
    const float* Wp   = (const float*)d_in[4];
    const float* bp   = (const float*)d_in[5];
    const float* Ws   = (const float*)d_in[6];
    const float* bs   = (const float*)d_in[7];
    const float* W_ih = (const float*)d_in[8];
    const float* b_ih = (const float*)d_in[9];
    const float* W_hh = (const float*)d_in[10];
    const float* b_hh = (const float*)d_in[11];
    const float* Wd1  = (const float*)d_in[12];
    const float* bd1  = (const float*)d_in[13];
    const float* Wd2  = (const float*)d_in[14];
    const float* bd2  = (const float*)d_in[15];
    float* out = (float*)d_out;

    prep_kernel<<<640, 256>>>(W_ih, b_ih, W_hh, b_hh, Wp, bp, Ws, bs, Wd1);

    const size_t smem_floats = 2 * (size_t)ASZ + 64 * 68 + 192 + 64 + 64 + 192 + 4;
    const size_t smem_bytes = smem_floats * sizeof(float);
    cudaFuncSetAttribute(gru_kernel, cudaFuncAttributeMaxDynamicSharedMemorySize,
                         (int)smem_bytes);

    gru_kernel<<<BATCH / MROWS, NTH, smem_bytes>>>(
        init_hidden, plan, gatep, init_state, bd1, Wd2, bd2, out);
}

// round 3
// speedup vs baseline: 4.1654x; 1.0732x over previous
#include <cuda_runtime.h>
#include <cstdint>

// Problem constants
#define BATCH   32768
#define TSTEPS  30
#define HID     384
#define KTOT    392     // 8 rowvec + 384 hidden
#define NKB     49      // K blocks of 8
#define NMAIN   144     // n8 fragments per kb in main B (24 ub * 6)
#define MROWS   64      // batch rows per CTA
#define NTH     256     // 8 warps
#define LDH     396     // sA row stride (392 + 4)
#define ASZ     (MROWS*LDH)

// -------- static device scratch --------
__device__ float2 g_B2[NKB * NMAIN * 32];   // main GEMM B (r,z,n_h), fragment order
__device__ float2 g_Bni[48 * 32];           // n_i B: kb=0 only, 24 ub * 2 n8
__device__ float2 g_Wd1f2[48 * 8 * 32];     // decode B, fragment order

__device__ __forceinline__ float to_tf32(float x) {
    unsigned u; asm("cvt.rna.tf32.f32 %0, %1;" : "=r"(u) : "f"(x));
    return __uint_as_float(u);
}
__device__ __forceinline__ float sigf(float x) { return 1.0f / (1.0f + __expf(-x)); }
__device__ __forceinline__ float tanhf_fast(float x) {
    return 2.0f / (1.0f + __expf(-2.0f * x)) - 1.0f;
}

__device__ __forceinline__ void mma_tf32(float* c, const unsigned* a, unsigned b0, unsigned b1) {
    asm volatile(
        "mma.sync.aligned.m16n8k8.row.col.f32.tf32.tf32.f32 "
        "{%0,%1,%2,%3}, {%4,%5,%6,%7}, {%8,%9}, {%0,%1,%2,%3};\n"
        : "+f"(c[0]), "+f"(c[1]), "+f"(c[2]), "+f"(c[3])
        : "r"(a[0]), "r"(a[1]), "r"(a[2]), "r"(a[3]), "r"(b0), "r"(b1));
}

// -------- prep helpers --------
// Main B column layout: col = ub*48 + gate*16 + uu,  gate: 0=r, 1=z, 2=n_h
// K rows: k<8 = rowvec [1, g, S0..2, gP0..2] coeffs; k>=8 = W_hh part.
__device__ float bval_main(int k, int ub, int colub,
                           const float* Wih, const float* bih,
                           const float* Whh, const float* bhh,
                           const float* Wp, const float* bp,
                           const float* Ws, const float* bs) {
    int gate = colub >> 4;          // 0=r,1=z,2=n_h
    int u = ub * 16 + (colub & 15);
    if (k >= 8) {
        int kk = k - 8;
        int grow = (gate == 2 ? 768 : gate * 384) + u;
        return Whh[grow * HID + kk];
    }
    if (gate == 2) return (k == 0) ? bhh[768 + u] : 0.0f;   // n_h: bias only
    int grow = gate * 384 + u;
    const float* wr = Wih + grow * 128;
    float s = 0.0f;
    if (k == 0) {
        s = bih[grow] + bhh[grow];
        for (int m = 0; m < 128; m++) s += bs[m] * wr[m];
    } else if (k == 1) {
        for (int m = 0; m < 128; m++) s += bp[m] * wr[m];
    } else if (k < 5) {
        int d = k - 2;
        for (int m = 0; m < 128; m++) s += Ws[m * 3 + d] * wr[m];
    } else {
        int d = k - 5;
        for (int m = 0; m < 128; m++) s += Wp[m * 3 + d] * wr[m];
    }
    return s;
}

// n_i: only the rowvec rows (k<8). u column index global.
__device__ float bval_ni(int k, int u,
                         const float* Wih, const float* bih,
                         const float* Wp, const float* bp,
                         const float* Ws, const float* bs) {
    int grow = 768 + u;
    const float* wr = Wih + grow * 128;
    float s = 0.0f;
    if (k == 0) {
        s = bih[grow];
        for (int m = 0; m < 128; m++) s += bs[m] * wr[m];
    } else if (k == 1) {
        for (int m = 0; m < 128; m++) s += bp[m] * wr[m];
    } else if (k < 5) {
        int d = k - 2;
        for (int m = 0; m < 128; m++) s += Ws[m * 3 + d] * wr[m];
    } else {
        int d = k - 5;
        for (int m = 0; m < 128; m++) s += Wp[m * 3 + d] * wr[m];
    }
    return s;
}

__global__ void prep_kernel(const float* __restrict__ W_ih, const float* __restrict__ b_ih,
                            const float* __restrict__ W_hh, const float* __restrict__ b_hh,
                            const float* __restrict__ Wp,  const float* __restrict__ bp,
                            const float* __restrict__ Ws,  const float* __restrict__ bs,
                            const float* __restrict__ Wd1) {
    int gid = blockIdx.x * blockDim.x + threadIdx.x;
    int nMain = NKB * NMAIN;
    int total = (nMain + 48 + 48 * 8) * 32;
    for (int w = gid; w < total; w += gridDim.x * blockDim.x) {
        int fid = w >> 5, lane = w & 31;
        int tig = lane & 3, g = lane >> 2;
        if (fid < nMain) {
            int kb = fid / NMAIN, rem = fid - kb * NMAIN;
            int ub = rem / 6, n8l = rem - ub * 6;
            int colub = n8l * 8 + g;
            float b0 = bval_main(kb * 8 + tig,     ub, colub, W_ih, b_ih, W_hh, b_hh, Wp, bp, Ws, bs);
            float b1 = bval_main(kb * 8 + tig + 4, ub, colub, W_ih, b_ih, W_hh, b_hh, Wp, bp, Ws, bs);
            g_B2[fid * 32 + lane] = make_float2(to_tf32(b0), to_tf32(b1));
        } else if (fid < nMain + 48) {
            int f = fid - nMain;            // ub*2 + n8l
            int ub = f >> 1, n8l = f & 1;
            int u = ub * 16 + n8l * 8 + g;
            float b0 = bval_ni(tig,     u, W_ih, b_ih, Wp, bp, Ws, bs);
            float b1 = bval_ni(tig + 4, u, W_ih, b_ih, Wp, bp, Ws, bs);
            g_Bni[f * 32 + lane] = make_float2(to_tf32(b0), to_tf32(b1));
        } else {
            int f = fid - nMain - 48;       // 48 kb * 8 n8
            int kb = f >> 3, n8 = f & 7;
            int n = n8 * 8 + g;
            int k = kb * 8 + tig;
            float b0 = Wd1[n * HID + k];
            float b1 = Wd1[n * HID + k + 4];
            g_Wd1f2[f * 32 + lane] = make_float2(to_tf32(b0), to_tf32(b1));
        }
    }
}

// -------- main fused GRU rollout --------
__global__ __launch_bounds__(NTH, 1)
void gru_kernel(const float* __restrict__ init_hidden,
                const float* __restrict__ plan,
                const float* __restrict__ gate,
                const float* __restrict__ init_state,
                const float* __restrict__ bd1,
                const float* __restrict__ Wd2,
                const float* __restrict__ bd2,
                float* __restrict__ out) {
    extern __shared__ float sm[];
    float* sA0   = sm;                  // [MROWS][LDH] ping
    float* sA1   = sA0 + ASZ;           // pong
    float* sDec  = sA1 + ASZ;           // [64][68]
    float* sStat = sDec + 64 * 68;      // [64*3]
    float* sGate = sStat + 192;         // [64]
    float* sbd1  = sGate + 64;          // [64]
    float* sWd2  = sbd1 + 64;           // [3*64]
    float* sbd2  = sWd2 + 192;          // [4]

    const int tid  = threadIdx.x;
    const int warp = tid >> 5;
    const int lane = tid & 31;
    const int g8   = lane >> 2;
    const int tig  = lane & 3;
    const int row0 = blockIdx.x * MROWS;

    for (int i = tid; i < MROWS * HID; i += NTH) {
        int r = i / HID, u = i - r * HID;
        sA0[r * LDH + 8 + u] = to_tf32(init_hidden[(size_t)row0 * HID + i]);
    }
    if (tid < 192) { sStat[tid] = init_state[(size_t)row0 * 3 + tid]; sWd2[tid] = Wd2[tid]; }
    if (tid < 64)  { sGate[tid] = gate[row0 + tid]; sbd1[tid] = bd1[tid]; }
    if (tid < 3)   sbd2[tid] = bd2[tid];
    __syncthreads();

    for (int t = 0; t < TSTEPS; t++) {
        float* Acur = (t & 1) ? sA1 : sA0;
        float* Anxt = (t & 1) ? sA0 : sA1;

        // ---- phase 0: rowvec = [1, g, S, g*P] into cols 0..7 ----
        for (int i = tid; i < MROWS * 8; i += NTH) {
            int r = i >> 3, c = i & 7;
            float v;
            if (c == 0)      v = 1.0f;
            else if (c == 1) v = sGate[r];
            else if (c < 5)  v = sStat[r * 3 + (c - 2)];
            else             v = sGate[r] * plan[((size_t)(row0 + r) * TSTEPS + t) * 3 + (c - 5)];
            Acur[r * LDH + c] = to_tf32(v);
        }
        __syncthreads();

        // ---- phase 1: GEMM (64 x 1152 dense + n_i micro) + gate math ----
        for (int task = 0; task < 3; task++) {
            const int ub = warp + task * 8;     // u-block 0..23
            float acc[96];                      // 4 mf x 6 n8 x 4  (r,z,n_h)
            float accN[32];                     // 4 mf x 2 n8 x 4  (n_i)
            #pragma unroll
            for (int i = 0; i < 96; i++) acc[i] = 0.0f;
            #pragma unroll
            for (int i = 0; i < 32; i++) accN[i] = 0.0f;

            const float2* Bp = g_B2 + (size_t)(ub * 6) * 32 + lane;
            float2 bb[2][6];
            #pragma unroll
            for (int j = 0; j < 6; j++) bb[0][j] = Bp[j * 32];
            float2 bni0 = g_Bni[(ub * 2 + 0) * 32 + lane];
            float2 bni1 = g_Bni[(ub * 2 + 1) * 32 + lane];

            #pragma unroll 2
            for (int kb = 0; kb < NKB; kb++) {
                const int cur = kb & 1;
                // prefetch next kb's B fragments
                if (kb < NKB - 1) {
                    const float2* Bn = Bp + (size_t)(kb + 1) * (NMAIN * 32);
                    #pragma unroll
                    for (int j = 0; j < 6; j++) bb[cur ^ 1][j] = Bn[j * 32];
                }
                // A fragments from shared
                unsigned a[16];
                const float* Ab = Acur + kb * 8;
                #pragma unroll
                for (int mf = 0; mf < 4; mf++) {
                    int r0 = mf * 16 + g8;
                    a[mf * 4 + 0] = __float_as_uint(Ab[r0 * LDH + tig]);
                    a[mf * 4 + 1] = __float_as_uint(Ab[(r0 + 8) * LDH + tig]);
                    a[mf * 4 + 2] = __float_as_uint(Ab[r0 * LDH + tig + 4]);
                    a[mf * 4 + 3] = __float_as_uint(Ab[(r0 + 8) * LDH + tig + 4]);
                }
                if (kb == 0) {   // n_i: rowvec-only contribution
                    unsigned n0x = __float_as_uint(bni0.x), n0y = __float_as_uint(bni0.y);
                    unsigned n1x = __float_as_uint(bni1.x), n1y = __float_as_uint(bni1.y);
                    #pragma unroll
                    for (int mf = 0; mf < 4; mf++) {
                        mma_tf32(&accN[(mf * 2 + 0) * 4], &a[mf * 4], n0x, n0y);
                        mma_tf32(&accN[(mf * 2 + 1) * 4], &a[mf * 4], n1x, n1y);
                    }
                }
                #pragma unroll
                for (int n8i = 0; n8i < 6; n8i++) {
                    unsigned b0 = __float_as_uint(bb[cur][n8i].x);
                    unsigned b1 = __float_as_uint(bb[cur][n8i].y);
                    #pragma unroll
                    for (int mf = 0; mf < 4; mf++)
                        mma_tf32(&acc[(mf * 6 + n8i) * 4], &a[mf * 4], b0, b1);
                }
            }

            // gate math on fragments
            #pragma unroll
            for (int mf = 0; mf < 4; mf++)
            #pragma unroll
            for (int half = 0; half < 2; half++)
            #pragma unroll
            for (int e = 0; e < 4; e++) {
                int row = mf * 16 + g8 + ((e >> 1) << 3);
                int u   = ub * 16 + half * 8 + tig * 2 + (e & 1);
                float aR  = acc[(mf * 6 + 0 + half) * 4 + e];
                float aZ  = acc[(mf * 6 + 2 + half) * 4 + e];
                float aNh = acc[(mf * 6 + 4 + half) * 4 + e];
                float aNi = accN[(mf * 2 + half) * 4 + e];
                float rg = sigf(aR);
                float zg = sigf(aZ);
                float n  = tanhf_fast(aNi + rg * aNh);
                float hold = Acur[row * LDH + 8 + u];
                float hnew = (1.0f - zg) * n + zg * hold;
                Anxt[row * LDH + 8 + u] = to_tf32(hnew);
            }
        }
        __syncthreads();

        // ---- phase 2: decode layer1 (64x64, K=384) ----
        {
            float dacc[16];
            #pragma unroll
            for (int i = 0; i < 16; i++) dacc[i] = 0.0f;
            #pragma unroll 2
            for (int kb = 0; kb < 48; kb++) {
                unsigned a[16];
                const float* Ab = Anxt + 8 + kb * 8;
                #pragma unroll
                for (int mf = 0; mf < 4; mf++) {
                    int r0 = mf * 16 + g8;
                    a[mf * 4 + 0] = __float_as_uint(Ab[r0 * LDH + tig]);
                    a[mf * 4 + 1] = __float_as_uint(Ab[(r0 + 8) * LDH + tig]);
                    a[mf * 4 + 2] = __float_as_uint(Ab[r0 * LDH + tig + 4]);
                    a[mf * 4 + 3] = __float_as_uint(Ab[(r0 + 8) * LDH + tig + 4]);
                }
                float2 bv = g_Wd1f2[(kb * 8 + warp) * 32 + lane];
                unsigned b0 = __float_as_uint(bv.x), b1 = __float_as_uint(bv.y);
                #pragma unroll
                for (int mf = 0; mf < 4; mf++)
                    mma_tf32(&dacc[mf * 4], &a[mf * 4], b0, b1);
            }
            #pragma unroll
            for (int mf = 0; mf < 4; mf++)
            #pragma unroll
            for (int e = 0; e < 4; e++) {
                int row = mf * 16 + g8 + ((e >> 1) << 3);
                int col = warp * 8 + tig * 2 + (e & 1);
                float v = dacc[mf * 4 + e] + sbd1[col];
                v = v > 0.0f ? v : (__expf(v) - 1.0f);   // ELU
                sDec[row * 68 + col] = v;
            }
        }
        __syncthreads();

        // ---- phase 3: decode layer2 + state update + output ----
        if (tid < 192) {
            int r = tid / 3, c = tid - r * 3;
            float acc = sbd2[c];
            const float* w2 = sWd2 + c * 64;
            const float* dp = sDec + r * 68;
            #pragma unroll 16
            for (int k = 0; k < 64; k++) acc += dp[k] * w2[k];
            float ns = sStat[tid] + acc;
            sStat[tid] = ns;
            out[((size_t)(row0 + r) * TSTEPS + t) * 3 + c] = ns;
        }
        __syncthreads();
    }
}

// -------- launch --------
extern "C" void kernel_launch(void* const* d_in, const int* in_sizes, int n_in,
                              void* d_out, int out_size) {
    const float* init_hidden = (const float*)d_in[0];
    const float* plan        = (const float*)d_in[1];
    const float* gatep       = (const float*)d_in[2];
    const float* init_state  = (const float*)d_in[3];
    const float* Wp   = (const float*)d_in[4];
    const float* bp   = (const float*)d_in[5];
    const float* Ws   = (const float*)d_in[6];
    const float* bs   = (const float*)d_in[7];
    const float* W_ih = (const float*)d_in[8];
    const float* b_ih = (const float*)d_in[9];
    const float* W_hh = (const float*)d_in[10];
    const float* b_hh = (const float*)d_in[11];
    const float* Wd1  = (const float*)d_in[12];
    const float* bd1  = (const float*)d_in[13];
    const float* Wd2  = (const float*)d_in[14];
    const float* bd2  = (const float*)d_in[15];
    float* out = (float*)d_out;

    prep_kernel<<<640, 256>>>(W_ih, b_ih, W_hh, b_hh, Wp, bp, Ws, bs, Wd1);

    const size_t smem_floats = 2 * (size_t)ASZ + 64 * 68 + 192 + 64 + 64 + 192 + 4;
    const size_t smem_bytes = smem_floats * sizeof(float);
    cudaFuncSetAttribute(gru_kernel, cudaFuncAttributeMaxDynamicSharedMemorySize,
                         (int)smem_bytes);

    gru_kernel<<<BATCH / MROWS, NTH, smem_bytes>>>(
        init_hidden, plan, gatep, init_state, bd1, Wd2, bd2, out);
}

// round 4
// speedup vs baseline: 4.9364x; 1.1851x over previous
#include <cuda_runtime.h>
#include <cstdint>

// Problem constants
#define BATCH   32768
#define TSTEPS  30
#define HID     384
#define KTOT    392     // 8 rowvec + 384 hidden
#define NKB     49      // K blocks of 8
#define NMAIN   144     // n8 fragments per kb in main B (24 ub * 6)
#define MROWS   64      // batch rows per CTA
#define NTH     512     // 16 warps
#define LDH     396     // sA row stride (392 + 4)
#define ASZ     (MROWS*LDH)

// -------- static device scratch --------
__device__ float2 g_B2[NKB * NMAIN * 32];   // main GEMM B (r,z,n_h), fragment order
__device__ float2 g_Bni[48 * 32];           // n_i B: kb=0 only, 24 ub * 2 n8
__device__ float2 g_Wd1f2[48 * 8 * 32];     // decode B, fragment order

__device__ __forceinline__ float to_tf32(float x) {
    unsigned u; asm("cvt.rna.tf32.f32 %0, %1;" : "=r"(u) : "f"(x));
    return __uint_as_float(u);
}
__device__ __forceinline__ float sigf(float x) { return 1.0f / (1.0f + __expf(-x)); }
__device__ __forceinline__ float tanhf_fast(float x) {
    return 2.0f / (1.0f + __expf(-2.0f * x)) - 1.0f;
}

__device__ __forceinline__ void mma_tf32(float* c, const unsigned* a, unsigned b0, unsigned b1) {
    asm volatile(
        "mma.sync.aligned.m16n8k8.row.col.f32.tf32.tf32.f32 "
        "{%0,%1,%2,%3}, {%4,%5,%6,%7}, {%8,%9}, {%0,%1,%2,%3};\n"
        : "+f"(c[0]), "+f"(c[1]), "+f"(c[2]), "+f"(c[3])
        : "r"(a[0]), "r"(a[1]), "r"(a[2]), "r"(a[3]), "r"(b0), "r"(b1));
}

// -------- prep helpers (unchanged layouts) --------
// Main B column layout: fragment (kb, ub, gate, uh) at index kb*NMAIN + ub*6 + gate*2 + uh
// K rows: k<8 = rowvec [1, g, S0..2, gP0..2] coeffs; k>=8 = W_hh part.
__device__ float bval_main(int k, int ub, int colub,
                           const float* Wih, const float* bih,
                           const float* Whh, const float* bhh,
                           const float* Wp, const float* bp,
                           const float* Ws, const float* bs) {
    int gate = colub >> 4;          // 0=r,1=z,2=n_h
    int u = ub * 16 + (colub & 15);
    if (k >= 8) {
        int kk = k - 8;
        int grow = (gate == 2 ? 768 : gate * 384) + u;
        return Whh[grow * HID + kk];
    }
    if (gate == 2) return (k == 0) ? bhh[768 + u] : 0.0f;   // n_h: bias only
    int grow = gate * 384 + u;
    const float* wr = Wih + grow * 128;
    float s = 0.0f;
    if (k == 0) {
        s = bih[grow] + bhh[grow];
        for (int m = 0; m < 128; m++) s += bs[m] * wr[m];
    } else if (k == 1) {
        for (int m = 0; m < 128; m++) s += bp[m] * wr[m];
    } else if (k < 5) {
        int d = k - 2;
        for (int m = 0; m < 128; m++) s += Ws[m * 3 + d] * wr[m];
    } else {
        int d = k - 5;
        for (int m = 0; m < 128; m++) s += Wp[m * 3 + d] * wr[m];
    }
    return s;
}

__device__ float bval_ni(int k, int u,
                         const float* Wih, const float* bih,
                         const float* Wp, const float* bp,
                         const float* Ws, const float* bs) {
    int grow = 768 + u;
    const float* wr = Wih + grow * 128;
    float s = 0.0f;
    if (k == 0) {
        s = bih[grow];
        for (int m = 0; m < 128; m++) s += bs[m] * wr[m];
    } else if (k == 1) {
        for (int m = 0; m < 128; m++) s += bp[m] * wr[m];
    } else if (k < 5) {
        int d = k - 2;
        for (int m = 0; m < 128; m++) s += Ws[m * 3 + d] * wr[m];
    } else {
        int d = k - 5;
        for (int m = 0; m < 128; m++) s += Wp[m * 3 + d] * wr[m];
    }
    return s;
}

__global__ void prep_kernel(const float* __restrict__ W_ih, const float* __restrict__ b_ih,
                            const float* __restrict__ W_hh, const float* __restrict__ b_hh,
                            const float* __restrict__ Wp,  const float* __restrict__ bp,
                            const float* __restrict__ Ws,  const float* __restrict__ bs,
                            const float* __restrict__ Wd1) {
    int gid = blockIdx.x * blockDim.x + threadIdx.x;
    int nMain = NKB * NMAIN;
    int total = (nMain + 48 + 48 * 8) * 32;
    for (int w = gid; w < total; w += gridDim.x * blockDim.x) {
        int fid = w >> 5, lane = w & 31;
        int tig = lane & 3, g = lane >> 2;
        if (fid < nMain) {
            int kb = fid / NMAIN, rem = fid - kb * NMAIN;
            int ub = rem / 6, n8l = rem - ub * 6;
            int colub = n8l * 8 + g;
            float b0 = bval_main(kb * 8 + tig,     ub, colub, W_ih, b_ih, W_hh, b_hh, Wp, bp, Ws, bs);
            float b1 = bval_main(kb * 8 + tig + 4, ub, colub, W_ih, b_ih, W_hh, b_hh, Wp, bp, Ws, bs);
            g_B2[fid * 32 + lane] = make_float2(to_tf32(b0), to_tf32(b1));
        } else if (fid < nMain + 48) {
            int f = fid - nMain;            // ub*2 + uh
            int ub = f >> 1, n8l = f & 1;
            int u = ub * 16 + n8l * 8 + g;
            float b0 = bval_ni(tig,     u, W_ih, b_ih, Wp, bp, Ws, bs);
            float b1 = bval_ni(tig + 4, u, W_ih, b_ih, Wp, bp, Ws, bs);
            g_Bni[f * 32 + lane] = make_float2(to_tf32(b0), to_tf32(b1));
        } else {
            int f = fid - nMain - 48;       // 48 kb * 8 n8
            int kb = f >> 3, n8 = f & 7;
            int n = n8 * 8 + g;
            int k = kb * 8 + tig;
            float b0 = Wd1[n * HID + k];
            float b1 = Wd1[n * HID + k + 4];
            g_Wd1f2[f * 32 + lane] = make_float2(to_tf32(b0), to_tf32(b1));
        }
    }
}

// -------- main fused GRU rollout: 16 warps, each owns 8-u sub-blocks --------
__global__ __launch_bounds__(NTH, 1)
void gru_kernel(const float* __restrict__ init_hidden,
                const float* __restrict__ plan,
                const float* __restrict__ gate,
                const float* __restrict__ init_state,
                const float* __restrict__ bd1,
                const float* __restrict__ Wd2,
                const float* __restrict__ bd2,
                float* __restrict__ out) {
    extern __shared__ float sm[];
    float* sA0   = sm;                  // [MROWS][LDH] ping
    float* sA1   = sA0 + ASZ;           // pong
    float* sDec  = sA1 + ASZ;           // [64][68]
    float* sStat = sDec + 64 * 68;      // [64*3]
    float* sGate = sStat + 192;         // [64]
    float* sbd1  = sGate + 64;          // [64]
    float* sWd2  = sbd1 + 64;           // [3*64]
    float* sbd2  = sWd2 + 192;          // [4]

    const int tid  = threadIdx.x;
    const int warp = tid >> 5;
    const int lane = tid & 31;
    const int g8   = lane >> 2;
    const int tig  = lane & 3;
    const int row0 = blockIdx.x * MROWS;

    for (int i = tid; i < MROWS * HID; i += NTH) {
        int r = i / HID, u = i - r * HID;
        sA0[r * LDH + 8 + u] = to_tf32(init_hidden[(size_t)row0 * HID + i]);
    }
    if (tid < 192) { sStat[tid] = init_state[(size_t)row0 * 3 + tid]; sWd2[tid] = Wd2[tid]; }
    if (tid < 64)  { sGate[tid] = gate[row0 + tid]; sbd1[tid] = bd1[tid]; }
    if (tid < 3)   sbd2[tid] = bd2[tid];
    __syncthreads();

    for (int t = 0; t < TSTEPS; t++) {
        float* Acur = (t & 1) ? sA1 : sA0;
        float* Anxt = (t & 1) ? sA0 : sA1;

        // ---- phase 0: rowvec = [1, g, S, g*P] into cols 0..7 ----
        if (tid < MROWS * 8) {
            int r = tid >> 3, c = tid & 7;
            float v;
            if (c == 0)      v = 1.0f;
            else if (c == 1) v = sGate[r];
            else if (c < 5)  v = sStat[r * 3 + (c - 2)];
            else             v = sGate[r] * plan[((size_t)(row0 + r) * TSTEPS + t) * 3 + (c - 5)];
            Acur[r * LDH + c] = to_tf32(v);
        }
        __syncthreads();

        // ---- phase 1: GEMM (64 x 1152 dense + n_i micro) + gate math ----
        // 16 warps x 3 tasks: each task = one 8-u sub-block (usb in [0,48))
        for (int task = 0; task < 3; task++) {
            const int usb = warp + task * 16;   // 0..47
            const int ub  = usb >> 1;
            const int uh  = usb & 1;

            float acc[48];                      // [mf][gate] x 4   (r,z,n_h)
            float accN[16];                     // [mf] x 4         (n_i)
            #pragma unroll
            for (int i = 0; i < 48; i++) acc[i] = 0.0f;
            #pragma unroll
            for (int i = 0; i < 16; i++) accN[i] = 0.0f;

            // fragment (kb, gate): g_B2[(kb*NMAIN + ub*6 + gate*2 + uh)*32 + lane]
            const float2* Bbase = g_B2 + (size_t)(ub * 6 + uh) * 32 + lane;
            float2 bb[2][3];
            #pragma unroll
            for (int gidx = 0; gidx < 3; gidx++) bb[0][gidx] = Bbase[gidx * 64];
            float2 bni = g_Bni[(ub * 2 + uh) * 32 + lane];

            #pragma unroll 2
            for (int kb = 0; kb < NKB; kb++) {
                const int cur = kb & 1;
                if (kb < NKB - 1) {
                    const float2* Bn = Bbase + (size_t)(kb + 1) * (NMAIN * 32);
                    #pragma unroll
                    for (int gidx = 0; gidx < 3; gidx++) bb[cur ^ 1][gidx] = Bn[gidx * 64];
                }
                unsigned a[16];
                const float* Ab = Acur + kb * 8;
                #pragma unroll
                for (int mf = 0; mf < 4; mf++) {
                    int r0 = mf * 16 + g8;
                    a[mf * 4 + 0] = __float_as_uint(Ab[r0 * LDH + tig]);
                    a[mf * 4 + 1] = __float_as_uint(Ab[(r0 + 8) * LDH + tig]);
                    a[mf * 4 + 2] = __float_as_uint(Ab[r0 * LDH + tig + 4]);
                    a[mf * 4 + 3] = __float_as_uint(Ab[(r0 + 8) * LDH + tig + 4]);
                }
                if (kb == 0) {   // n_i: rowvec-only contribution
                    unsigned nx = __float_as_uint(bni.x), ny = __float_as_uint(bni.y);
                    #pragma unroll
                    for (int mf = 0; mf < 4; mf++)
                        mma_tf32(&accN[mf * 4], &a[mf * 4], nx, ny);
                }
                #pragma unroll
                for (int gidx = 0; gidx < 3; gidx++) {
                    unsigned b0 = __float_as_uint(bb[cur][gidx].x);
                    unsigned b1 = __float_as_uint(bb[cur][gidx].y);
                    #pragma unroll
                    for (int mf = 0; mf < 4; mf++)
                        mma_tf32(&acc[(mf * 3 + gidx) * 4], &a[mf * 4], b0, b1);
                }
            }

            // gate math on fragments
            #pragma unroll
            for (int mf = 0; mf < 4; mf++)
            #pragma unroll
            for (int e = 0; e < 4; e++) {
                int row = mf * 16 + g8 + ((e >> 1) << 3);
                int u   = usb * 8 + tig * 2 + (e & 1);
                float aR  = acc[(mf * 3 + 0) * 4 + e];
                float aZ  = acc[(mf * 3 + 1) * 4 + e];
                float aNh = acc[(mf * 3 + 2) * 4 + e];
                float aNi = accN[mf * 4 + e];
                float rg = sigf(aR);
                float zg = sigf(aZ);
                float n  = tanhf_fast(aNi + rg * aNh);
                float hold = Acur[row * LDH + 8 + u];
                float hnew = (1.0f - zg) * n + zg * hold;
                Anxt[row * LDH + 8 + u] = to_tf32(hnew);
            }
        }
        __syncthreads();

        // ---- phase 2: decode layer1 (64x64, K=384), M split across warp halves ----
        {
            const int c8 = warp & 7;        // column block (8 cols)
            const int mh = warp >> 3;       // M half: rows [mh*32, mh*32+32)
            float dacc[8];
            #pragma unroll
            for (int i = 0; i < 8; i++) dacc[i] = 0.0f;

            float2 bv = g_Wd1f2[(0 * 8 + c8) * 32 + lane];
            #pragma unroll 2
            for (int kb = 0; kb < 48; kb++) {
                float2 bcur = bv;
                if (kb < 47) bv = g_Wd1f2[((kb + 1) * 8 + c8) * 32 + lane];
                unsigned a[8];
                const float* Ab = Anxt + 8 + kb * 8;
                #pragma unroll
                for (int mf2 = 0; mf2 < 2; mf2++) {
                    int r0 = (mh * 2 + mf2) * 16 + g8;
                    a[mf2 * 4 + 0] = __float_as_uint(Ab[r0 * LDH + tig]);
                    a[mf2 * 4 + 1] = __float_as_uint(Ab[(r0 + 8) * LDH + tig]);
                    a[mf2 * 4 + 2] = __float_as_uint(Ab[r0 * LDH + tig + 4]);
                    a[mf2 * 4 + 3] = __float_as_uint(Ab[(r0 + 8) * LDH + tig + 4]);
                }
                unsigned b0 = __float_as_uint(bcur.x), b1 = __float_as_uint(bcur.y);
                #pragma unroll
                for (int mf2 = 0; mf2 < 2; mf2++)
                    mma_tf32(&dacc[mf2 * 4], &a[mf2 * 4], b0, b1);
            }
            #pragma unroll
            for (int mf2 = 0; mf2 < 2; mf2++)
            #pragma unroll
            for (int e = 0; e < 4; e++) {
                int row = (mh * 2 + mf2) * 16 + g8 + ((e >> 1) << 3);
                int col = c8 * 8 + tig * 2 + (e & 1);
                float v = dacc[mf2 * 4 + e] + sbd1[col];
                v = v > 0.0f ? v : (__expf(v) - 1.0f);   // ELU
                sDec[row * 68 + col] = v;
            }
        }
        __syncthreads();

        // ---- phase 3: decode layer2 + state update + output ----
        if (tid < 192) {
            int r = tid / 3, c = tid - r * 3;
            float acc = sbd2[c];
            const float* w2 = sWd2 + c * 64;
            const float* dp = sDec + r * 68;
            #pragma unroll 16
            for (int k = 0; k < 64; k++) acc += dp[k] * w2[k];
            float ns = sStat[tid] + acc;
            sStat[tid] = ns;
            out[((size_t)(row0 + r) * TSTEPS + t) * 3 + c] = ns;
        }
        __syncthreads();
    }
}

// -------- launch --------
extern "C" void kernel_launch(void* const* d_in, const int* in_sizes, int n_in,
                              void* d_out, int out_size) {
    const float* init_hidden = (const float*)d_in[0];
    const float* plan        = (const float*)d_in[1];
    const float* gatep       = (const float*)d_in[2];
    const float* init_state  = (const float*)d_in[3];
    const float* Wp   = (const float*)d_in[4];
    const float* bp   = (const float*)d_in[5];
    const float* Ws   = (const float*)d_in[6];
    const float* bs   = (const float*)d_in[7];
    const float* W_ih = (const float*)d_in[8];
    const float* b_ih = (const float*)d_in[9];
    const float* W_hh = (const float*)d_in[10];
    const float* b_hh = (const float*)d_in[11];
    const float* Wd1  = (const float*)d_in[12];
    const float* bd1  = (const float*)d_in[13];
    const float* Wd2  = (const float*)d_in[14];
    const float* bd2  = (const float*)d_in[15];
    float* out = (float*)d_out;

    prep_kernel<<<640, 256>>>(W_ih, b_ih, W_hh, b_hh, Wp, bp, Ws, bs, Wd1);

    const size_t smem_floats = 2 * (size_t)ASZ + 64 * 68 + 192 + 64 + 64 + 192 + 4;
    const size_t smem_bytes = smem_floats * sizeof(float);
    cudaFuncSetAttribute(gru_kernel, cudaFuncAttributeMaxDynamicSharedMemorySize,
                         (int)smem_bytes);

    gru_kernel<<<BATCH / MROWS, NTH, smem_bytes>>>(
        init_hidden, plan, gatep, init_state, bd1, Wd2, bd2, out);
}